// round 14
// baseline (speedup 1.0000x reference)
#include <cuda_runtime.h>
#include <cuda_fp16.h>
#include <cstdint>

// ===========================================================================
// LSTM attention cell via mma.sync fp16 (single-pass fp16 operands, f32 accum)
// B=4096, E=H=C=1024, D=3072. out = [pred | hidden | cell]
// R13 structure + dynamic tile scheduling via global atomic counters.
// ===========================================================================

#define BHsz (4096ull * 1024ull)

__device__ __half g_Af [4096ull * 3072];   // [emb|hid|ctx] K=3072
__device__ __half g_Wf [4096ull * 3072];   // rows Wi,Wf,Wo,Wg stacked
__device__ __half g_Ahc[4096ull * 2048];   // [hidden|ctx]  K=2048
__device__ __half g_Bhc[1024ull * 2048];   // rows [Wh|Wc]
__device__ __half g_Wpf[1024ull * 1024];   // Wp
__device__ __half g_res[4096ull * 1024];   // resid fp16
__device__ float g_gates[4ull * 4096ull * 1024];   // activated i,f,o,g (fp32)
__device__ float g_biascat[4096];                  // [bi|bf|bo|bg]
__device__ int   g_tctr[3];                        // tile counters per GEMM

// ------------------------------ helpers ------------------------------------
__device__ __forceinline__ uint32_t smem_u32(const void* p) {
    uint32_t a;
    asm("{ .reg .u64 t; cvta.to.shared.u64 t, %1; cvt.u32.u64 %0, t; }"
        : "=r"(a) : "l"(p));
    return a;
}
__device__ __forceinline__ void cp_async16(uint32_t s, const void* g) {
    asm volatile("cp.async.cg.shared.global [%0], [%1], 16;\n"
                 :: "r"(s), "l"(g) : "memory");
}
__device__ __forceinline__ void cp_commit() {
    asm volatile("cp.async.commit_group;\n" ::: "memory");
}
template <int N>
__device__ __forceinline__ void cp_wait() {
    asm volatile("cp.async.wait_group %0;\n" :: "n"(N) : "memory");
}
__device__ __forceinline__ void ldsm4(uint32_t (&r)[4], uint32_t addr) {
    asm volatile("ldmatrix.sync.aligned.m8n8.x4.shared.b16 {%0,%1,%2,%3}, [%4];"
                 : "=r"(r[0]), "=r"(r[1]), "=r"(r[2]), "=r"(r[3]) : "r"(addr));
}
__device__ __forceinline__ void mma16816(float (&c)[4], const uint32_t (&a)[4],
                                         uint32_t b0, uint32_t b1) {
    asm volatile(
        "mma.sync.aligned.m16n8k16.row.col.f32.f16.f16.f32 "
        "{%0,%1,%2,%3}, {%4,%5,%6,%7}, {%8,%9}, {%0,%1,%2,%3};"
        : "+f"(c[0]), "+f"(c[1]), "+f"(c[2]), "+f"(c[3])
        : "r"(a[0]), "r"(a[1]), "r"(a[2]), "r"(a[3]), "r"(b0), "r"(b1));
}
__device__ __forceinline__ float sigm(float x) { return 1.0f / (1.0f + __expf(-x)); }
__device__ __forceinline__ float tanh_fast(float x) {
    const float ax = fabsf(x);
    const float e = __expf(-2.0f * ax);
    const float r = (1.0f - e) / (1.0f + e);
    return copysignf(r, x);
}
// float4 -> 4 fp16 -> uint2 (8-byte store), elements consecutive
__device__ __forceinline__ void cvt_store4(__half* dst, float4 v) {
    __half2 a = __floats2half2_rn(v.x, v.y);
    __half2 b = __floats2half2_rn(v.z, v.w);
    uint2 u;
    u.x = reinterpret_cast<uint32_t&>(a);
    u.y = reinterpret_cast<uint32_t&>(b);
    *reinterpret_cast<uint2*>(dst) = u;
}

// ===========================================================================
// GEMM: C = A @ B^T, plain fp16 operands, persistent CTAs + dynamic tiles.
// Block 128x128, 8 warps (2x4), warp tile m64 x n32, k-chunk 64, 3-stage pipe.
// M tiles fixed at 32 (M=4096): tile t -> bm=(t&31)*128, bn=(t>>5)*128.
// MODE 0: gates -> g_gates fp32 (bias0, sigmoid/tanh by n>>10)
// MODE 1: resid -> g_res fp16 (bias0+bias1+addend)
// MODE 2: pred  -> outf (bias0)
// ===========================================================================
template <int MODE>
__global__ void __launch_bounds__(256, 2)
gemm_ms(const __half* __restrict__ Af, const __half* __restrict__ Bf,
        int arow_len, int brow_len, int nchunks, int ntile_total,
        const float* __restrict__ bias0, const float* __restrict__ bias1,
        const float* __restrict__ addend, float* __restrict__ outf,
        __half* __restrict__ outh)
{
    extern __shared__ char smem_raw[];
    const uint32_t sbase = smem_u32(smem_raw);
    constexpr uint32_t STAGE = 256 * 128;   // 32 KB: A rows 0-127, B rows 128-255
    __shared__ int s_t;

    const int tid = threadIdx.x, wid = tid >> 5, lane = tid & 31;
    const int wm = wid & 1, wn = wid >> 1;          // 2 x 4 warps
    const int r0 = tid >> 3, u0 = tid & 7;
    const int g = lane >> 3, l7 = lane & 7;
    const int tg = lane >> 2, tl = lane & 3;

    for (;;) {
        if (tid == 0) s_t = atomicAdd(&g_tctr[MODE], 1);
        __syncthreads();
        const int t = s_t;
        if (t >= ntile_total) break;

        const long bm = (long)(t & 31) * 128;
        const long bn = (long)(t >> 5) * 128;

        float acc[4][4][4];
        #pragma unroll
        for (int f = 0; f < 4; ++f)
            #pragma unroll
            for (int n = 0; n < 4; ++n)
                #pragma unroll
                for (int e = 0; e < 4; ++e) acc[f][n][e] = 0.0f;

        auto load_chunk = [&](int c, int stg) {
            const uint32_t sb = sbase + (uint32_t)stg * STAGE;
            #pragma unroll
            for (int j = 0; j < 4; ++j) {           // A rows (64 k = 128 B/row)
                const int row = r0 + j * 32;
                const __half* src = Af + (size_t)(bm + row) * arow_len
                                       + (size_t)c * 64 + u0 * 8;
                cp_async16(sb + row * 128 + ((u0 ^ (row & 7)) << 4), src);
            }
            #pragma unroll
            for (int j = 0; j < 4; ++j) {           // B rows
                const int row = r0 + j * 32;
                const __half* src = Bf + (size_t)(bn + row) * brow_len
                                       + (size_t)c * 64 + u0 * 8;
                const int srow = row + 128;
                cp_async16(sb + srow * 128 + ((u0 ^ (srow & 7)) << 4), src);
            }
            cp_commit();
        };

        load_chunk(0, 0);
        load_chunk(1, 1);

        for (int c = 0; c < nchunks; ++c) {
            cp_wait<1>();
            __syncthreads();                       // single sync per chunk

            if (c + 2 < nchunks) load_chunk(c + 2, (c + 2) % 3);
            else cp_commit();

            const uint32_t sb = sbase + (uint32_t)(c % 3) * STAGE;
            #pragma unroll
            for (int s = 0; s < 4; ++s) {          // four k16 steps per chunk
                uint32_t Aq[4][4];
                #pragma unroll
                for (int f = 0; f < 4; ++f) {
                    const int row = wm * 64 + f * 16 + ((g & 1) << 3) + l7;
                    const int ch = 2 * s + (g >> 1);
                    ldsm4(Aq[f], sb + row * 128 + ((ch ^ (row & 7)) << 4));
                }
                #pragma unroll
                for (int p = 0; p < 2; ++p) {      // two n16 groups
                    const int row = 128 + wn * 32 + p * 16 + ((g >> 1) << 3) + l7;
                    const int ch = 2 * s + (g & 1);
                    uint32_t Bq[4];
                    ldsm4(Bq, sb + row * 128 + ((ch ^ (row & 7)) << 4));
                    #pragma unroll
                    for (int f = 0; f < 4; ++f) {
                        mma16816(acc[f][2 * p],     Aq[f], Bq[0], Bq[1]);
                        mma16816(acc[f][2 * p + 1], Aq[f], Bq[2], Bq[3]);
                    }
                }
            }
        }

        // ---------------------------- epilogue -----------------------------
        #pragma unroll
        for (int f = 0; f < 4; ++f) {
            #pragma unroll
            for (int nf = 0; nf < 4; ++nf) {
                const long n = bn + wn * 32 + nf * 8 + tl * 2;
                #pragma unroll
                for (int h = 0; h < 2; ++h) {
                    const long m = bm + wm * 64 + f * 16 + tg + h * 8;
                    float v0 = acc[f][nf][2 * h + 0];
                    float v1 = acc[f][nf][2 * h + 1];
                    if (MODE == 0) {
                        v0 += bias0[n]; v1 += bias0[n + 1];
                        const int gate = (int)(n >> 10);
                        if (gate < 3) { v0 = sigm(v0); v1 = sigm(v1); }
                        else          { v0 = tanh_fast(v0); v1 = tanh_fast(v1); }
                        float* d = g_gates + (size_t)gate * BHsz
                                 + (size_t)m * 1024 + (n & 1023);
                        d[0] = v0; d[1] = v1;
                    } else if (MODE == 1) {
                        const float* ar = addend + (size_t)m * 1024;
                        v0 += bias0[n] + bias1[n] + ar[n];
                        v1 += bias0[n + 1] + bias1[n + 1] + ar[n + 1];
                        __half2 hv = __floats2half2_rn(v0, v1);
                        *reinterpret_cast<__half2*>(outh + (size_t)m * 1024 + n) = hv;
                    } else {
                        float* d = outf + (size_t)m * 1024 + n;
                        d[0] = v0 + bias0[n];
                        d[1] = v1 + bias0[n + 1];
                    }
                }
            }
        }
    }
}

// --------------- single merged conversion kernel (one launch) --------------
// blocks [0,4096)        : A/Ahc conversion (+ block 0 resets tile counters)
// blocks [4096,8192)     : W rows
// blocks [8192,8704)     : [Wh|Wc] rows (2 rows/block)
// blocks [8704,8960)     : Wp
// blocks [8960,8976)     : bias concat
__global__ void convAll(const float* __restrict__ emb, const float* __restrict__ hid,
                        const float* __restrict__ ctx,
                        const float* __restrict__ Wi, const float* __restrict__ Wf,
                        const float* __restrict__ Wo, const float* __restrict__ Wg,
                        const float* __restrict__ Wh, const float* __restrict__ Wc,
                        const float* __restrict__ Wp,
                        const float* __restrict__ bi, const float* __restrict__ bf,
                        const float* __restrict__ bo, const float* __restrict__ bg)
{
    const int b = blockIdx.x;
    if (b == 0 && threadIdx.x < 3) g_tctr[threadIdx.x] = 0;
    if (b < 4096) {
        const size_t i4 = (size_t)b * 256 + threadIdx.x;       // B*1024/4
        const size_t m = i4 >> 8, c = (i4 & 255) * 4;
        float4 v0 = *reinterpret_cast<const float4*>(emb + m * 1024 + c);
        float4 v1 = *reinterpret_cast<const float4*>(hid + m * 1024 + c);
        float4 v2 = *reinterpret_cast<const float4*>(ctx + m * 1024 + c);
        cvt_store4(g_Af + m * 3072 + c, v0);
        cvt_store4(g_Af + m * 3072 + 1024 + c, v1);
        cvt_store4(g_Af + m * 3072 + 2048 + c, v2);
        cvt_store4(g_Ahc + m * 2048 + 1024 + c, v2);
    } else if (b < 8192) {
        const int r = b - 4096;                                // 0..4095
        const int sel = r >> 10;
        const float* W = (sel == 0) ? Wi : (sel == 1) ? Wf : (sel == 2) ? Wo : Wg;
        const float* src = W + (size_t)(r & 1023) * 3072;
        __half* dst = g_Wf + (size_t)r * 3072;
        float4 v0 = *reinterpret_cast<const float4*>(src + (size_t)threadIdx.x * 4);
        float4 v1 = *reinterpret_cast<const float4*>(src + (size_t)(threadIdx.x + 256) * 4);
        float4 v2 = *reinterpret_cast<const float4*>(src + (size_t)(threadIdx.x + 512) * 4);
        cvt_store4(dst + (size_t)threadIdx.x * 4, v0);
        cvt_store4(dst + (size_t)(threadIdx.x + 256) * 4, v1);
        cvt_store4(dst + (size_t)(threadIdx.x + 512) * 4, v2);
    } else if (b < 8704) {
        const int r0 = (b - 8192) * 2;                         // 0..1022
        #pragma unroll
        for (int rr = 0; rr < 2; ++rr) {
            const int r = r0 + rr;
            __half* dst = g_Bhc + (size_t)r * 2048;
            const size_t cA = (size_t)threadIdx.x * 4;
            float4 vA = *reinterpret_cast<const float4*>(Wh + (size_t)r * 1024 + cA);
            float4 vB = *reinterpret_cast<const float4*>(Wc + (size_t)r * 1024 + cA);
            cvt_store4(dst + cA, vA);
            cvt_store4(dst + cA + 1024, vB);
        }
    } else if (b < 8960) {
        const size_t base = (size_t)(b - 8704) * 256 + threadIdx.x;  // 0..65535
        const size_t S = 65536;
        float4 v0 = *reinterpret_cast<const float4*>(Wp + (base + 0 * S) * 4);
        float4 v1 = *reinterpret_cast<const float4*>(Wp + (base + 1 * S) * 4);
        float4 v2 = *reinterpret_cast<const float4*>(Wp + (base + 2 * S) * 4);
        float4 v3 = *reinterpret_cast<const float4*>(Wp + (base + 3 * S) * 4);
        cvt_store4(g_Wpf + (base + 0 * S) * 4, v0);
        cvt_store4(g_Wpf + (base + 1 * S) * 4, v1);
        cvt_store4(g_Wpf + (base + 2 * S) * 4, v2);
        cvt_store4(g_Wpf + (base + 3 * S) * 4, v3);
    } else {
        const int i = (b - 8960) * 256 + threadIdx.x;          // 4096
        const int sel = i >> 10, c = i & 1023;
        const float* bb = (sel == 0) ? bi : (sel == 1) ? bf : (sel == 2) ? bo : bg;
        g_biascat[i] = bb[c];
    }
}

// cell = f*c_prev + i*g ; hidden = o*tanh(cell); fp16 hidden into Ahc
__global__ void cellhid_kernel(const float* __restrict__ cprev, float* __restrict__ out)
{
    const size_t i = ((size_t)blockIdx.x * blockDim.x + threadIdx.x) * 4;
    float4 gi = *(const float4*)&g_gates[i];
    float4 gf = *(const float4*)&g_gates[BHsz + i];
    float4 go = *(const float4*)&g_gates[2 * BHsz + i];
    float4 gg = *(const float4*)&g_gates[3 * BHsz + i];
    float4 cp = *(const float4*)&cprev[i];
    float4 c, h;
    c.x = gf.x * cp.x + gi.x * gg.x;  h.x = go.x * tanh_fast(c.x);
    c.y = gf.y * cp.y + gi.y * gg.y;  h.y = go.y * tanh_fast(c.y);
    c.z = gf.z * cp.z + gi.z * gg.z;  h.z = go.z * tanh_fast(c.z);
    c.w = gf.w * cp.w + gi.w * gg.w;  h.w = go.w * tanh_fast(c.w);
    *(float4*)&out[BHsz + i]     = h;
    *(float4*)&out[2 * BHsz + i] = c;
    const size_t m = i >> 10, c0 = i & 1023;
    cvt_store4(g_Ahc + m * 2048 + c0, h);
}

// ---------------------------------------------------------------------------
extern "C" void kernel_launch(void* const* d_in, const int* in_sizes, int n_in,
                              void* d_out, int out_size)
{
    const float* emb   = (const float*)d_in[0];
    const float* hid   = (const float*)d_in[1];
    const float* cprev = (const float*)d_in[2];
    const float* ctx   = (const float*)d_in[3];
    const float* Wi = (const float*)d_in[4];  const float* bi = (const float*)d_in[5];
    const float* Wf = (const float*)d_in[6];  const float* bf = (const float*)d_in[7];
    const float* Wo = (const float*)d_in[8];  const float* bo = (const float*)d_in[9];
    const float* Wg = (const float*)d_in[10]; const float* bg = (const float*)d_in[11];
    const float* Wc = (const float*)d_in[12]; const float* bc = (const float*)d_in[13];
    const float* Wh = (const float*)d_in[14]; const float* bh = (const float*)d_in[15];
    const float* Wp = (const float*)d_in[16]; const float* bp = (const float*)d_in[17];
    float* out = (float*)d_out;

    static bool init = false;
    static __half *Af, *Wf_, *Ahc, *Bhc, *Wpf, *res;
    static float *biascat;
    if (!init) {
        cudaGetSymbolAddress((void**)&Af, g_Af);
        cudaGetSymbolAddress((void**)&Wf_, g_Wf);
        cudaGetSymbolAddress((void**)&Ahc, g_Ahc);
        cudaGetSymbolAddress((void**)&Bhc, g_Bhc);
        cudaGetSymbolAddress((void**)&Wpf, g_Wpf);
        cudaGetSymbolAddress((void**)&res, g_res);
        cudaGetSymbolAddress((void**)&biascat, g_biascat);
        cudaFuncSetAttribute(gemm_ms<0>, cudaFuncAttributeMaxDynamicSharedMemorySize, 98304);
        cudaFuncSetAttribute(gemm_ms<1>, cudaFuncAttributeMaxDynamicSharedMemorySize, 98304);
        cudaFuncSetAttribute(gemm_ms<2>, cudaFuncAttributeMaxDynamicSharedMemorySize, 98304);
        init = true;
    }

    // 1) fp32 -> fp16 conversions (single launch; also resets tile counters)
    convAll<<<8976, 256>>>(emb, hid, ctx, Wi, Wf, Wo, Wg, Wh, Wc, Wp,
                           bi, bf, bo, bg);

    // 2) gates GEMM 4096x4096x3072 -> activated g_gates (dynamic, 1024 tiles)
    gemm_ms<0><<<296, 256, 98304>>>(
        Af, Wf_, 3072, 3072, 48, 1024, biascat, nullptr, nullptr, nullptr, nullptr);

    // 3) cell/hidden elementwise (+ fp16 hidden into Ahc)
    cellhid_kernel<<<(int)(BHsz / 4 / 256), 256>>>(cprev, out);

    // 4) resid = emb + [hidden|ctx]@[Wh|Wc]^T + bh + bc -> g_res (fp16)
    gemm_ms<1><<<296, 256, 98304>>>(
        Ahc, Bhc, 2048, 2048, 32, 256, bh, bc, emb, nullptr, res);

    // 5) pred = resid@Wp^T + bp -> out[0..BH)
    gemm_ms<2><<<296, 256, 98304>>>(
        res, Wpf, 1024, 1024, 16, 256, bp, nullptr, nullptr, out, nullptr);
}

// round 15
// speedup vs baseline: 1.1993x; 1.1993x over previous
#include <cuda_runtime.h>
#include <cuda_fp16.h>
#include <cstdint>

// ===========================================================================
// LSTM attention cell via mma.sync fp16 (single-pass fp16 operands, f32 accum)
// B=4096, E=H=C=1024, D=3072. out = [pred | hidden | cell]
// R13 structure (static persistent tiles, fp32 gates, merged conv launch)
// + inter-tile prologue prefetch (next tile's chunks 0/1 issued pre-epilogue).
// ===========================================================================

#define BHsz (4096ull * 1024ull)

__device__ __half g_Af [4096ull * 3072];   // [emb|hid|ctx] K=3072
__device__ __half g_Wf [4096ull * 3072];   // rows Wi,Wf,Wo,Wg stacked
__device__ __half g_Ahc[4096ull * 2048];   // [hidden|ctx]  K=2048
__device__ __half g_Bhc[1024ull * 2048];   // rows [Wh|Wc]
__device__ __half g_Wpf[1024ull * 1024];   // Wp
__device__ __half g_res[4096ull * 1024];   // resid fp16
__device__ float g_gates[4ull * 4096ull * 1024];   // activated i,f,o,g (fp32)
__device__ float g_biascat[4096];                  // [bi|bf|bo|bg]

// ------------------------------ helpers ------------------------------------
__device__ __forceinline__ uint32_t smem_u32(const void* p) {
    uint32_t a;
    asm("{ .reg .u64 t; cvta.to.shared.u64 t, %1; cvt.u32.u64 %0, t; }"
        : "=r"(a) : "l"(p));
    return a;
}
__device__ __forceinline__ void cp_async16(uint32_t s, const void* g) {
    asm volatile("cp.async.cg.shared.global [%0], [%1], 16;\n"
                 :: "r"(s), "l"(g) : "memory");
}
__device__ __forceinline__ void cp_commit() {
    asm volatile("cp.async.commit_group;\n" ::: "memory");
}
template <int N>
__device__ __forceinline__ void cp_wait() {
    asm volatile("cp.async.wait_group %0;\n" :: "n"(N) : "memory");
}
__device__ __forceinline__ void ldsm4(uint32_t (&r)[4], uint32_t addr) {
    asm volatile("ldmatrix.sync.aligned.m8n8.x4.shared.b16 {%0,%1,%2,%3}, [%4];"
                 : "=r"(r[0]), "=r"(r[1]), "=r"(r[2]), "=r"(r[3]) : "r"(addr));
}
__device__ __forceinline__ void mma16816(float (&c)[4], const uint32_t (&a)[4],
                                         uint32_t b0, uint32_t b1) {
    asm volatile(
        "mma.sync.aligned.m16n8k16.row.col.f32.f16.f16.f32 "
        "{%0,%1,%2,%3}, {%4,%5,%6,%7}, {%8,%9}, {%0,%1,%2,%3};"
        : "+f"(c[0]), "+f"(c[1]), "+f"(c[2]), "+f"(c[3])
        : "r"(a[0]), "r"(a[1]), "r"(a[2]), "r"(a[3]), "r"(b0), "r"(b1));
}
__device__ __forceinline__ float sigm(float x) { return 1.0f / (1.0f + __expf(-x)); }
__device__ __forceinline__ float tanh_fast(float x) {
    const float ax = fabsf(x);
    const float e = __expf(-2.0f * ax);
    const float r = (1.0f - e) / (1.0f + e);
    return copysignf(r, x);
}
// float4 -> 4 fp16 -> uint2 (8-byte store), elements consecutive
__device__ __forceinline__ void cvt_store4(__half* dst, float4 v) {
    __half2 a = __floats2half2_rn(v.x, v.y);
    __half2 b = __floats2half2_rn(v.z, v.w);
    uint2 u;
    u.x = reinterpret_cast<uint32_t&>(a);
    u.y = reinterpret_cast<uint32_t&>(b);
    *reinterpret_cast<uint2*>(dst) = u;
}

// ===========================================================================
// GEMM: C = A @ B^T, plain fp16 operands, persistent tiles (static stride).
// Block 128x128, 8 warps (2x4), warp tile m64 x n32, k-chunk 64, 3-stage pipe.
// M tiles fixed at 32 (M=4096): tile t -> bm=(t&31)*128, bn=(t>>5)*128.
// MODE 0: gates -> g_gates fp32 (bias0, sigmoid/tanh by n>>10)
// MODE 1: resid -> g_res fp16 (bias0+bias1+addend)
// MODE 2: pred  -> outf (bias0)
// ===========================================================================
template <int MODE>
__global__ void __launch_bounds__(256, 2)
gemm_ms(const __half* __restrict__ Af, const __half* __restrict__ Bf,
        int arow_len, int brow_len, int nchunks, int ntile_total,
        const float* __restrict__ bias0, const float* __restrict__ bias1,
        const float* __restrict__ addend, float* __restrict__ outf,
        __half* __restrict__ outh)
{
    extern __shared__ char smem_raw[];
    const uint32_t sbase = smem_u32(smem_raw);
    constexpr uint32_t STAGE = 256 * 128;   // 32 KB: A rows 0-127, B rows 128-255

    const int tid = threadIdx.x, wid = tid >> 5, lane = tid & 31;
    const int wm = wid & 1, wn = wid >> 1;          // 2 x 4 warps
    const int r0 = tid >> 3, u0 = tid & 7;
    const int g = lane >> 3, l7 = lane & 7;
    const int tg = lane >> 2, tl = lane & 3;

    // load chunk c of tile (tbm, tbn) into pipeline stage stg
    auto load_chunk = [&](int c, int stg, long tbm, long tbn) {
        const uint32_t sb = sbase + (uint32_t)stg * STAGE;
        #pragma unroll
        for (int j = 0; j < 4; ++j) {           // A rows (64 k = 128 B/row)
            const int row = r0 + j * 32;
            const __half* src = Af + (size_t)(tbm + row) * arow_len
                                   + (size_t)c * 64 + u0 * 8;
            cp_async16(sb + row * 128 + ((u0 ^ (row & 7)) << 4), src);
        }
        #pragma unroll
        for (int j = 0; j < 4; ++j) {           // B rows
            const int row = r0 + j * 32;
            const __half* src = Bf + (size_t)(tbn + row) * brow_len
                                   + (size_t)c * 64 + u0 * 8;
            const int srow = row + 128;
            cp_async16(sb + srow * 128 + ((u0 ^ (srow & 7)) << 4), src);
        }
        cp_commit();
    };

    bool preloaded = false;

    for (int t = blockIdx.x; t < ntile_total; t += gridDim.x) {
        const long bm = (long)(t & 31) * 128;
        const long bn = (long)(t >> 5) * 128;

        float acc[4][4][4];
        #pragma unroll
        for (int f = 0; f < 4; ++f)
            #pragma unroll
            for (int n = 0; n < 4; ++n)
                #pragma unroll
                for (int e = 0; e < 4; ++e) acc[f][n][e] = 0.0f;

        if (!preloaded) {
            load_chunk(0, 0, bm, bn);
            load_chunk(1, 1, bm, bn);
        }

        for (int c = 0; c < nchunks; ++c) {
            cp_wait<1>();
            __syncthreads();                       // single sync per chunk

            if (c + 2 < nchunks) load_chunk(c + 2, (c + 2) % 3, bm, bn);
            else cp_commit();

            const uint32_t sb = sbase + (uint32_t)(c % 3) * STAGE;
            #pragma unroll
            for (int s = 0; s < 4; ++s) {          // four k16 steps per chunk
                uint32_t Aq[4][4];
                #pragma unroll
                for (int f = 0; f < 4; ++f) {
                    const int row = wm * 64 + f * 16 + ((g & 1) << 3) + l7;
                    const int ch = 2 * s + (g >> 1);
                    ldsm4(Aq[f], sb + row * 128 + ((ch ^ (row & 7)) << 4));
                }
                #pragma unroll
                for (int p = 0; p < 2; ++p) {      // two n16 groups
                    const int row = 128 + wn * 32 + p * 16 + ((g >> 1) << 3) + l7;
                    const int ch = 2 * s + (g & 1);
                    uint32_t Bq[4];
                    ldsm4(Bq, sb + row * 128 + ((ch ^ (row & 7)) << 4));
                    #pragma unroll
                    for (int f = 0; f < 4; ++f) {
                        mma16816(acc[f][2 * p],     Aq[f], Bq[0], Bq[1]);
                        mma16816(acc[f][2 * p + 1], Aq[f], Bq[2], Bq[3]);
                    }
                }
            }
        }

        // All warps done reading smem -> safe to prefetch next tile's chunks
        __syncthreads();
        const int tn = t + gridDim.x;
        if (tn < ntile_total) {
            const long bm2 = (long)(tn & 31) * 128;
            const long bn2 = (long)(tn >> 5) * 128;
            load_chunk(0, 0, bm2, bn2);
            load_chunk(1, 1, bm2, bn2);
            preloaded = true;
        }

        // ---------------------------- epilogue -----------------------------
        #pragma unroll
        for (int f = 0; f < 4; ++f) {
            #pragma unroll
            for (int nf = 0; nf < 4; ++nf) {
                const long n = bn + wn * 32 + nf * 8 + tl * 2;
                #pragma unroll
                for (int h = 0; h < 2; ++h) {
                    const long m = bm + wm * 64 + f * 16 + tg + h * 8;
                    float v0 = acc[f][nf][2 * h + 0];
                    float v1 = acc[f][nf][2 * h + 1];
                    if (MODE == 0) {
                        v0 += bias0[n]; v1 += bias0[n + 1];
                        const int gate = (int)(n >> 10);
                        if (gate < 3) { v0 = sigm(v0); v1 = sigm(v1); }
                        else          { v0 = tanh_fast(v0); v1 = tanh_fast(v1); }
                        float* d = g_gates + (size_t)gate * BHsz
                                 + (size_t)m * 1024 + (n & 1023);
                        d[0] = v0; d[1] = v1;
                    } else if (MODE == 1) {
                        const float* ar = addend + (size_t)m * 1024;
                        v0 += bias0[n] + bias1[n] + ar[n];
                        v1 += bias0[n + 1] + bias1[n + 1] + ar[n + 1];
                        __half2 hv = __floats2half2_rn(v0, v1);
                        *reinterpret_cast<__half2*>(outh + (size_t)m * 1024 + n) = hv;
                    } else {
                        float* d = outf + (size_t)m * 1024 + n;
                        d[0] = v0 + bias0[n];
                        d[1] = v1 + bias0[n + 1];
                    }
                }
            }
        }
    }
}

// --------------- single merged conversion kernel (one launch) --------------
// blocks [0,4096)        : A/Ahc conversion
// blocks [4096,8192)     : W rows
// blocks [8192,8704)     : [Wh|Wc] rows (2 rows/block)
// blocks [8704,8960)     : Wp
// blocks [8960,8976)     : bias concat
__global__ void convAll(const float* __restrict__ emb, const float* __restrict__ hid,
                        const float* __restrict__ ctx,
                        const float* __restrict__ Wi, const float* __restrict__ Wf,
                        const float* __restrict__ Wo, const float* __restrict__ Wg,
                        const float* __restrict__ Wh, const float* __restrict__ Wc,
                        const float* __restrict__ Wp,
                        const float* __restrict__ bi, const float* __restrict__ bf,
                        const float* __restrict__ bo, const float* __restrict__ bg)
{
    const int b = blockIdx.x;
    if (b < 4096) {
        const size_t i4 = (size_t)b * 256 + threadIdx.x;       // B*1024/4
        const size_t m = i4 >> 8, c = (i4 & 255) * 4;
        float4 v0 = *reinterpret_cast<const float4*>(emb + m * 1024 + c);
        float4 v1 = *reinterpret_cast<const float4*>(hid + m * 1024 + c);
        float4 v2 = *reinterpret_cast<const float4*>(ctx + m * 1024 + c);
        cvt_store4(g_Af + m * 3072 + c, v0);
        cvt_store4(g_Af + m * 3072 + 1024 + c, v1);
        cvt_store4(g_Af + m * 3072 + 2048 + c, v2);
        cvt_store4(g_Ahc + m * 2048 + 1024 + c, v2);
    } else if (b < 8192) {
        const int r = b - 4096;                                // 0..4095
        const int sel = r >> 10;
        const float* W = (sel == 0) ? Wi : (sel == 1) ? Wf : (sel == 2) ? Wo : Wg;
        const float* src = W + (size_t)(r & 1023) * 3072;
        __half* dst = g_Wf + (size_t)r * 3072;
        float4 v0 = *reinterpret_cast<const float4*>(src + (size_t)threadIdx.x * 4);
        float4 v1 = *reinterpret_cast<const float4*>(src + (size_t)(threadIdx.x + 256) * 4);
        float4 v2 = *reinterpret_cast<const float4*>(src + (size_t)(threadIdx.x + 512) * 4);
        cvt_store4(dst + (size_t)threadIdx.x * 4, v0);
        cvt_store4(dst + (size_t)(threadIdx.x + 256) * 4, v1);
        cvt_store4(dst + (size_t)(threadIdx.x + 512) * 4, v2);
    } else if (b < 8704) {
        const int r0 = (b - 8192) * 2;                         // 0..1022
        #pragma unroll
        for (int rr = 0; rr < 2; ++rr) {
            const int r = r0 + rr;
            __half* dst = g_Bhc + (size_t)r * 2048;
            const size_t cA = (size_t)threadIdx.x * 4;
            float4 vA = *reinterpret_cast<const float4*>(Wh + (size_t)r * 1024 + cA);
            float4 vB = *reinterpret_cast<const float4*>(Wc + (size_t)r * 1024 + cA);
            cvt_store4(dst + cA, vA);
            cvt_store4(dst + cA + 1024, vB);
        }
    } else if (b < 8960) {
        const size_t base = (size_t)(b - 8704) * 256 + threadIdx.x;  // 0..65535
        const size_t S = 65536;
        float4 v0 = *reinterpret_cast<const float4*>(Wp + (base + 0 * S) * 4);
        float4 v1 = *reinterpret_cast<const float4*>(Wp + (base + 1 * S) * 4);
        float4 v2 = *reinterpret_cast<const float4*>(Wp + (base + 2 * S) * 4);
        float4 v3 = *reinterpret_cast<const float4*>(Wp + (base + 3 * S) * 4);
        cvt_store4(g_Wpf + (base + 0 * S) * 4, v0);
        cvt_store4(g_Wpf + (base + 1 * S) * 4, v1);
        cvt_store4(g_Wpf + (base + 2 * S) * 4, v2);
        cvt_store4(g_Wpf + (base + 3 * S) * 4, v3);
    } else {
        const int i = (b - 8960) * 256 + threadIdx.x;          // 4096
        const int sel = i >> 10, c = i & 1023;
        const float* bb = (sel == 0) ? bi : (sel == 1) ? bf : (sel == 2) ? bo : bg;
        g_biascat[i] = bb[c];
    }
}

// cell = f*c_prev + i*g ; hidden = o*tanh(cell); fp16 hidden into Ahc
__global__ void cellhid_kernel(const float* __restrict__ cprev, float* __restrict__ out)
{
    const size_t i = ((size_t)blockIdx.x * blockDim.x + threadIdx.x) * 4;
    float4 gi = *(const float4*)&g_gates[i];
    float4 gf = *(const float4*)&g_gates[BHsz + i];
    float4 go = *(const float4*)&g_gates[2 * BHsz + i];
    float4 gg = *(const float4*)&g_gates[3 * BHsz + i];
    float4 cp = *(const float4*)&cprev[i];
    float4 c, h;
    c.x = gf.x * cp.x + gi.x * gg.x;  h.x = go.x * tanh_fast(c.x);
    c.y = gf.y * cp.y + gi.y * gg.y;  h.y = go.y * tanh_fast(c.y);
    c.z = gf.z * cp.z + gi.z * gg.z;  h.z = go.z * tanh_fast(c.z);
    c.w = gf.w * cp.w + gi.w * gg.w;  h.w = go.w * tanh_fast(c.w);
    *(float4*)&out[BHsz + i]     = h;
    *(float4*)&out[2 * BHsz + i] = c;
    const size_t m = i >> 10, c0 = i & 1023;
    cvt_store4(g_Ahc + m * 2048 + c0, h);
}

// ---------------------------------------------------------------------------
extern "C" void kernel_launch(void* const* d_in, const int* in_sizes, int n_in,
                              void* d_out, int out_size)
{
    const float* emb   = (const float*)d_in[0];
    const float* hid   = (const float*)d_in[1];
    const float* cprev = (const float*)d_in[2];
    const float* ctx   = (const float*)d_in[3];
    const float* Wi = (const float*)d_in[4];  const float* bi = (const float*)d_in[5];
    const float* Wf = (const float*)d_in[6];  const float* bf = (const float*)d_in[7];
    const float* Wo = (const float*)d_in[8];  const float* bo = (const float*)d_in[9];
    const float* Wg = (const float*)d_in[10]; const float* bg = (const float*)d_in[11];
    const float* Wc = (const float*)d_in[12]; const float* bc = (const float*)d_in[13];
    const float* Wh = (const float*)d_in[14]; const float* bh = (const float*)d_in[15];
    const float* Wp = (const float*)d_in[16]; const float* bp = (const float*)d_in[17];
    float* out = (float*)d_out;

    static bool init = false;
    static __half *Af, *Wf_, *Ahc, *Bhc, *Wpf, *res;
    static float *biascat;
    if (!init) {
        cudaGetSymbolAddress((void**)&Af, g_Af);
        cudaGetSymbolAddress((void**)&Wf_, g_Wf);
        cudaGetSymbolAddress((void**)&Ahc, g_Ahc);
        cudaGetSymbolAddress((void**)&Bhc, g_Bhc);
        cudaGetSymbolAddress((void**)&Wpf, g_Wpf);
        cudaGetSymbolAddress((void**)&res, g_res);
        cudaGetSymbolAddress((void**)&biascat, g_biascat);
        cudaFuncSetAttribute(gemm_ms<0>, cudaFuncAttributeMaxDynamicSharedMemorySize, 98304);
        cudaFuncSetAttribute(gemm_ms<1>, cudaFuncAttributeMaxDynamicSharedMemorySize, 98304);
        cudaFuncSetAttribute(gemm_ms<2>, cudaFuncAttributeMaxDynamicSharedMemorySize, 98304);
        init = true;
    }

    // 1) fp32 -> fp16 conversions (single launch)
    convAll<<<8976, 256>>>(emb, hid, ctx, Wi, Wf, Wo, Wg, Wh, Wc, Wp,
                           bi, bf, bo, bg);

    // 2) gates GEMM 4096x4096x3072 -> activated g_gates (persistent, 1024 tiles)
    gemm_ms<0><<<296, 256, 98304>>>(
        Af, Wf_, 3072, 3072, 48, 1024, biascat, nullptr, nullptr, nullptr, nullptr);

    // 3) cell/hidden elementwise (+ fp16 hidden into Ahc)
    cellhid_kernel<<<(int)(BHsz / 4 / 256), 256>>>(cprev, out);

    // 4) resid = emb + [hidden|ctx]@[Wh|Wc]^T + bh + bc -> g_res (fp16)
    gemm_ms<1><<<256, 256, 98304>>>(
        Ahc, Bhc, 2048, 2048, 32, 256, bh, bc, emb, nullptr, res);

    // 5) pred = resid@Wp^T + bp -> out[0..BH)
    gemm_ms<2><<<256, 256, 98304>>>(
        res, Wpf, 1024, 1024, 16, 256, bp, nullptr, nullptr, out, nullptr);
}

// round 16
// speedup vs baseline: 1.2039x; 1.0039x over previous
#include <cuda_runtime.h>
#include <cuda_fp16.h>
#include <cstdint>

// ===========================================================================
// LSTM attention cell via mma.sync fp16 (single-pass fp16 operands, f32 accum)
// B=4096, E=H=C=1024, D=3072. out = [pred | hidden | cell]
// R13 structure (static persistent tiles, fp32 gates, merged conv launch)
// + A-fragment double-buffering across k16 steps (hide ldsm latency).
// ===========================================================================

#define BHsz (4096ull * 1024ull)

__device__ __half g_Af [4096ull * 3072];   // [emb|hid|ctx] K=3072
__device__ __half g_Wf [4096ull * 3072];   // rows Wi,Wf,Wo,Wg stacked
__device__ __half g_Ahc[4096ull * 2048];   // [hidden|ctx]  K=2048
__device__ __half g_Bhc[1024ull * 2048];   // rows [Wh|Wc]
__device__ __half g_Wpf[1024ull * 1024];   // Wp
__device__ __half g_res[4096ull * 1024];   // resid fp16
__device__ float g_gates[4ull * 4096ull * 1024];   // activated i,f,o,g (fp32)
__device__ float g_biascat[4096];                  // [bi|bf|bo|bg]

// ------------------------------ helpers ------------------------------------
__device__ __forceinline__ uint32_t smem_u32(const void* p) {
    uint32_t a;
    asm("{ .reg .u64 t; cvta.to.shared.u64 t, %1; cvt.u32.u64 %0, t; }"
        : "=r"(a) : "l"(p));
    return a;
}
__device__ __forceinline__ void cp_async16(uint32_t s, const void* g) {
    asm volatile("cp.async.cg.shared.global [%0], [%1], 16;\n"
                 :: "r"(s), "l"(g) : "memory");
}
__device__ __forceinline__ void cp_commit() {
    asm volatile("cp.async.commit_group;\n" ::: "memory");
}
template <int N>
__device__ __forceinline__ void cp_wait() {
    asm volatile("cp.async.wait_group %0;\n" :: "n"(N) : "memory");
}
__device__ __forceinline__ void ldsm4(uint32_t (&r)[4], uint32_t addr) {
    asm volatile("ldmatrix.sync.aligned.m8n8.x4.shared.b16 {%0,%1,%2,%3}, [%4];"
                 : "=r"(r[0]), "=r"(r[1]), "=r"(r[2]), "=r"(r[3]) : "r"(addr));
}
__device__ __forceinline__ void mma16816(float (&c)[4], const uint32_t (&a)[4],
                                         uint32_t b0, uint32_t b1) {
    asm volatile(
        "mma.sync.aligned.m16n8k16.row.col.f32.f16.f16.f32 "
        "{%0,%1,%2,%3}, {%4,%5,%6,%7}, {%8,%9}, {%0,%1,%2,%3};"
        : "+f"(c[0]), "+f"(c[1]), "+f"(c[2]), "+f"(c[3])
        : "r"(a[0]), "r"(a[1]), "r"(a[2]), "r"(a[3]), "r"(b0), "r"(b1));
}
__device__ __forceinline__ float sigm(float x) { return 1.0f / (1.0f + __expf(-x)); }
__device__ __forceinline__ float tanh_fast(float x) {
    const float ax = fabsf(x);
    const float e = __expf(-2.0f * ax);
    const float r = (1.0f - e) / (1.0f + e);
    return copysignf(r, x);
}
// float4 -> 4 fp16 -> uint2 (8-byte store), elements consecutive
__device__ __forceinline__ void cvt_store4(__half* dst, float4 v) {
    __half2 a = __floats2half2_rn(v.x, v.y);
    __half2 b = __floats2half2_rn(v.z, v.w);
    uint2 u;
    u.x = reinterpret_cast<uint32_t&>(a);
    u.y = reinterpret_cast<uint32_t&>(b);
    *reinterpret_cast<uint2*>(dst) = u;
}

// ===========================================================================
// GEMM: C = A @ B^T, plain fp16 operands, persistent tiles (static stride).
// Block 128x128, 8 warps (2x4), warp tile m64 x n32, k-chunk 64, 3-stage pipe.
// A fragments double-buffered across the four k16 steps of each chunk.
// M tiles fixed at 32 (M=4096): tile t -> bm=(t&31)*128, bn=(t>>5)*128.
// MODE 0: gates -> g_gates fp32 (bias0, sigmoid/tanh by n>>10)
// MODE 1: resid -> g_res fp16 (bias0+bias1+addend)
// MODE 2: pred  -> outf (bias0)
// ===========================================================================
template <int MODE>
__global__ void __launch_bounds__(256, 2)
gemm_ms(const __half* __restrict__ Af, const __half* __restrict__ Bf,
        int arow_len, int brow_len, int nchunks, int ntile_total,
        const float* __restrict__ bias0, const float* __restrict__ bias1,
        const float* __restrict__ addend, float* __restrict__ outf,
        __half* __restrict__ outh)
{
    extern __shared__ char smem_raw[];
    const uint32_t sbase = smem_u32(smem_raw);
    constexpr uint32_t STAGE = 256 * 128;   // 32 KB: A rows 0-127, B rows 128-255

    const int tid = threadIdx.x, wid = tid >> 5, lane = tid & 31;
    const int wm = wid & 1, wn = wid >> 1;          // 2 x 4 warps
    const int r0 = tid >> 3, u0 = tid & 7;
    const int g = lane >> 3, l7 = lane & 7;
    const int tg = lane >> 2, tl = lane & 3;

    for (int t = blockIdx.x; t < ntile_total; t += gridDim.x) {
        const long bm = (long)(t & 31) * 128;
        const long bn = (long)(t >> 5) * 128;

        float acc[4][4][4];
        #pragma unroll
        for (int f = 0; f < 4; ++f)
            #pragma unroll
            for (int n = 0; n < 4; ++n)
                #pragma unroll
                for (int e = 0; e < 4; ++e) acc[f][n][e] = 0.0f;

        auto load_chunk = [&](int c, int stg) {
            const uint32_t sb = sbase + (uint32_t)stg * STAGE;
            #pragma unroll
            for (int j = 0; j < 4; ++j) {           // A rows (64 k = 128 B/row)
                const int row = r0 + j * 32;
                const __half* src = Af + (size_t)(bm + row) * arow_len
                                       + (size_t)c * 64 + u0 * 8;
                cp_async16(sb + row * 128 + ((u0 ^ (row & 7)) << 4), src);
            }
            #pragma unroll
            for (int j = 0; j < 4; ++j) {           // B rows
                const int row = r0 + j * 32;
                const __half* src = Bf + (size_t)(bn + row) * brow_len
                                       + (size_t)c * 64 + u0 * 8;
                const int srow = row + 128;
                cp_async16(sb + srow * 128 + ((u0 ^ (srow & 7)) << 4), src);
            }
            cp_commit();
        };

        load_chunk(0, 0);
        load_chunk(1, 1);

        for (int c = 0; c < nchunks; ++c) {
            cp_wait<1>();
            __syncthreads();                       // single sync per chunk

            if (c + 2 < nchunks) load_chunk(c + 2, (c + 2) % 3);
            else cp_commit();

            const uint32_t sb = sbase + (uint32_t)(c % 3) * STAGE;

            uint32_t Aq[2][4][4];                  // double-buffered A frags
            // preload step 0's A fragments
            #pragma unroll
            for (int f = 0; f < 4; ++f) {
                const int row = wm * 64 + f * 16 + ((g & 1) << 3) + l7;
                const int ch = (g >> 1);           // s = 0
                ldsm4(Aq[0][f], sb + row * 128 + ((ch ^ (row & 7)) << 4));
            }

            #pragma unroll
            for (int s = 0; s < 4; ++s) {          // four k16 steps per chunk
                const int cur = s & 1;
                if (s < 3) {                       // prefetch next step's A
                    #pragma unroll
                    for (int f = 0; f < 4; ++f) {
                        const int row = wm * 64 + f * 16 + ((g & 1) << 3) + l7;
                        const int ch = 2 * (s + 1) + (g >> 1);
                        ldsm4(Aq[cur ^ 1][f],
                              sb + row * 128 + ((ch ^ (row & 7)) << 4));
                    }
                }
                #pragma unroll
                for (int p = 0; p < 2; ++p) {      // two n16 groups
                    const int row = 128 + wn * 32 + p * 16 + ((g >> 1) << 3) + l7;
                    const int ch = 2 * s + (g & 1);
                    uint32_t Bq[4];
                    ldsm4(Bq, sb + row * 128 + ((ch ^ (row & 7)) << 4));
                    #pragma unroll
                    for (int f = 0; f < 4; ++f) {
                        mma16816(acc[f][2 * p],     Aq[cur][f], Bq[0], Bq[1]);
                        mma16816(acc[f][2 * p + 1], Aq[cur][f], Bq[2], Bq[3]);
                    }
                }
            }
        }

        // ---------------------------- epilogue -----------------------------
        #pragma unroll
        for (int f = 0; f < 4; ++f) {
            #pragma unroll
            for (int nf = 0; nf < 4; ++nf) {
                const long n = bn + wn * 32 + nf * 8 + tl * 2;
                #pragma unroll
                for (int h = 0; h < 2; ++h) {
                    const long m = bm + wm * 64 + f * 16 + tg + h * 8;
                    float v0 = acc[f][nf][2 * h + 0];
                    float v1 = acc[f][nf][2 * h + 1];
                    if (MODE == 0) {
                        v0 += bias0[n]; v1 += bias0[n + 1];
                        const int gate = (int)(n >> 10);
                        if (gate < 3) { v0 = sigm(v0); v1 = sigm(v1); }
                        else          { v0 = tanh_fast(v0); v1 = tanh_fast(v1); }
                        float* d = g_gates + (size_t)gate * BHsz
                                 + (size_t)m * 1024 + (n & 1023);
                        d[0] = v0; d[1] = v1;
                    } else if (MODE == 1) {
                        const float* ar = addend + (size_t)m * 1024;
                        v0 += bias0[n] + bias1[n] + ar[n];
                        v1 += bias0[n + 1] + bias1[n + 1] + ar[n + 1];
                        __half2 hv = __floats2half2_rn(v0, v1);
                        *reinterpret_cast<__half2*>(outh + (size_t)m * 1024 + n) = hv;
                    } else {
                        float* d = outf + (size_t)m * 1024 + n;
                        d[0] = v0 + bias0[n];
                        d[1] = v1 + bias0[n + 1];
                    }
                }
            }
        }
    }
}

// --------------- single merged conversion kernel (one launch) --------------
// blocks [0,4096)        : A/Ahc conversion
// blocks [4096,8192)     : W rows
// blocks [8192,8704)     : [Wh|Wc] rows (2 rows/block)
// blocks [8704,8960)     : Wp
// blocks [8960,8976)     : bias concat
__global__ void convAll(const float* __restrict__ emb, const float* __restrict__ hid,
                        const float* __restrict__ ctx,
                        const float* __restrict__ Wi, const float* __restrict__ Wf,
                        const float* __restrict__ Wo, const float* __restrict__ Wg,
                        const float* __restrict__ Wh, const float* __restrict__ Wc,
                        const float* __restrict__ Wp,
                        const float* __restrict__ bi, const float* __restrict__ bf,
                        const float* __restrict__ bo, const float* __restrict__ bg)
{
    const int b = blockIdx.x;
    if (b < 4096) {
        const size_t i4 = (size_t)b * 256 + threadIdx.x;       // B*1024/4
        const size_t m = i4 >> 8, c = (i4 & 255) * 4;
        float4 v0 = *reinterpret_cast<const float4*>(emb + m * 1024 + c);
        float4 v1 = *reinterpret_cast<const float4*>(hid + m * 1024 + c);
        float4 v2 = *reinterpret_cast<const float4*>(ctx + m * 1024 + c);
        cvt_store4(g_Af + m * 3072 + c, v0);
        cvt_store4(g_Af + m * 3072 + 1024 + c, v1);
        cvt_store4(g_Af + m * 3072 + 2048 + c, v2);
        cvt_store4(g_Ahc + m * 2048 + 1024 + c, v2);
    } else if (b < 8192) {
        const int r = b - 4096;                                // 0..4095
        const int sel = r >> 10;
        const float* W = (sel == 0) ? Wi : (sel == 1) ? Wf : (sel == 2) ? Wo : Wg;
        const float* src = W + (size_t)(r & 1023) * 3072;
        __half* dst = g_Wf + (size_t)r * 3072;
        float4 v0 = *reinterpret_cast<const float4*>(src + (size_t)threadIdx.x * 4);
        float4 v1 = *reinterpret_cast<const float4*>(src + (size_t)(threadIdx.x + 256) * 4);
        float4 v2 = *reinterpret_cast<const float4*>(src + (size_t)(threadIdx.x + 512) * 4);
        cvt_store4(dst + (size_t)threadIdx.x * 4, v0);
        cvt_store4(dst + (size_t)(threadIdx.x + 256) * 4, v1);
        cvt_store4(dst + (size_t)(threadIdx.x + 512) * 4, v2);
    } else if (b < 8704) {
        const int r0 = (b - 8192) * 2;                         // 0..1022
        #pragma unroll
        for (int rr = 0; rr < 2; ++rr) {
            const int r = r0 + rr;
            __half* dst = g_Bhc + (size_t)r * 2048;
            const size_t cA = (size_t)threadIdx.x * 4;
            float4 vA = *reinterpret_cast<const float4*>(Wh + (size_t)r * 1024 + cA);
            float4 vB = *reinterpret_cast<const float4*>(Wc + (size_t)r * 1024 + cA);
            cvt_store4(dst + cA, vA);
            cvt_store4(dst + cA + 1024, vB);
        }
    } else if (b < 8960) {
        const size_t base = (size_t)(b - 8704) * 256 + threadIdx.x;  // 0..65535
        const size_t S = 65536;
        float4 v0 = *reinterpret_cast<const float4*>(Wp + (base + 0 * S) * 4);
        float4 v1 = *reinterpret_cast<const float4*>(Wp + (base + 1 * S) * 4);
        float4 v2 = *reinterpret_cast<const float4*>(Wp + (base + 2 * S) * 4);
        float4 v3 = *reinterpret_cast<const float4*>(Wp + (base + 3 * S) * 4);
        cvt_store4(g_Wpf + (base + 0 * S) * 4, v0);
        cvt_store4(g_Wpf + (base + 1 * S) * 4, v1);
        cvt_store4(g_Wpf + (base + 2 * S) * 4, v2);
        cvt_store4(g_Wpf + (base + 3 * S) * 4, v3);
    } else {
        const int i = (b - 8960) * 256 + threadIdx.x;          // 4096
        const int sel = i >> 10, c = i & 1023;
        const float* bb = (sel == 0) ? bi : (sel == 1) ? bf : (sel == 2) ? bo : bg;
        g_biascat[i] = bb[c];
    }
}

// cell = f*c_prev + i*g ; hidden = o*tanh(cell); fp16 hidden into Ahc
__global__ void cellhid_kernel(const float* __restrict__ cprev, float* __restrict__ out)
{
    const size_t i = ((size_t)blockIdx.x * blockDim.x + threadIdx.x) * 4;
    float4 gi = *(const float4*)&g_gates[i];
    float4 gf = *(const float4*)&g_gates[BHsz + i];
    float4 go = *(const float4*)&g_gates[2 * BHsz + i];
    float4 gg = *(const float4*)&g_gates[3 * BHsz + i];
    float4 cp = *(const float4*)&cprev[i];
    float4 c, h;
    c.x = gf.x * cp.x + gi.x * gg.x;  h.x = go.x * tanh_fast(c.x);
    c.y = gf.y * cp.y + gi.y * gg.y;  h.y = go.y * tanh_fast(c.y);
    c.z = gf.z * cp.z + gi.z * gg.z;  h.z = go.z * tanh_fast(c.z);
    c.w = gf.w * cp.w + gi.w * gg.w;  h.w = go.w * tanh_fast(c.w);
    *(float4*)&out[BHsz + i]     = h;
    *(float4*)&out[2 * BHsz + i] = c;
    const size_t m = i >> 10, c0 = i & 1023;
    cvt_store4(g_Ahc + m * 2048 + c0, h);
}

// ---------------------------------------------------------------------------
extern "C" void kernel_launch(void* const* d_in, const int* in_sizes, int n_in,
                              void* d_out, int out_size)
{
    const float* emb   = (const float*)d_in[0];
    const float* hid   = (const float*)d_in[1];
    const float* cprev = (const float*)d_in[2];
    const float* ctx   = (const float*)d_in[3];
    const float* Wi = (const float*)d_in[4];  const float* bi = (const float*)d_in[5];
    const float* Wf = (const float*)d_in[6];  const float* bf = (const float*)d_in[7];
    const float* Wo = (const float*)d_in[8];  const float* bo = (const float*)d_in[9];
    const float* Wg = (const float*)d_in[10]; const float* bg = (const float*)d_in[11];
    const float* Wc = (const float*)d_in[12]; const float* bc = (const float*)d_in[13];
    const float* Wh = (const float*)d_in[14]; const float* bh = (const float*)d_in[15];
    const float* Wp = (const float*)d_in[16]; const float* bp = (const float*)d_in[17];
    float* out = (float*)d_out;

    static bool init = false;
    static __half *Af, *Wf_, *Ahc, *Bhc, *Wpf, *res;
    static float *biascat;
    if (!init) {
        cudaGetSymbolAddress((void**)&Af, g_Af);
        cudaGetSymbolAddress((void**)&Wf_, g_Wf);
        cudaGetSymbolAddress((void**)&Ahc, g_Ahc);
        cudaGetSymbolAddress((void**)&Bhc, g_Bhc);
        cudaGetSymbolAddress((void**)&Wpf, g_Wpf);
        cudaGetSymbolAddress((void**)&res, g_res);
        cudaGetSymbolAddress((void**)&biascat, g_biascat);
        cudaFuncSetAttribute(gemm_ms<0>, cudaFuncAttributeMaxDynamicSharedMemorySize, 98304);
        cudaFuncSetAttribute(gemm_ms<1>, cudaFuncAttributeMaxDynamicSharedMemorySize, 98304);
        cudaFuncSetAttribute(gemm_ms<2>, cudaFuncAttributeMaxDynamicSharedMemorySize, 98304);
        init = true;
    }

    // 1) fp32 -> fp16 conversions (single launch)
    convAll<<<8976, 256>>>(emb, hid, ctx, Wi, Wf, Wo, Wg, Wh, Wc, Wp,
                           bi, bf, bo, bg);

    // 2) gates GEMM 4096x4096x3072 -> activated g_gates (persistent, 1024 tiles)
    gemm_ms<0><<<296, 256, 98304>>>(
        Af, Wf_, 3072, 3072, 48, 1024, biascat, nullptr, nullptr, nullptr, nullptr);

    // 3) cell/hidden elementwise (+ fp16 hidden into Ahc)
    cellhid_kernel<<<(int)(BHsz / 4 / 256), 256>>>(cprev, out);

    // 4) resid = emb + [hidden|ctx]@[Wh|Wc]^T + bh + bc -> g_res (fp16)
    gemm_ms<1><<<256, 256, 98304>>>(
        Ahc, Bhc, 2048, 2048, 32, 256, bh, bc, emb, nullptr, res);

    // 5) pred = resid@Wp^T + bp -> out[0..BH)
    gemm_ms<2><<<256, 256, 98304>>>(
        res, Wpf, 1024, 1024, 16, 256, bp, nullptr, nullptr, out, nullptr);
}